// round 1
// baseline (speedup 1.0000x reference)
#include <cuda_runtime.h>

#define NN 100000
#define EE 3200000
#define HH 64
#define GGB 256
#define DOUTC 12

// ---------------- scratch (static device allocations, allowed) ----------------
__device__ float g_h[NN * HH];
__device__ float g_out0[NN * HH];
__device__ float g_T[NN * 320];
__device__ float g_m[NN * HH];
__device__ float g_gx[NN * 192];
__device__ float g_gh[NN * 192];
__device__ float g_A1[NN * HH];
__device__ float g_I[NN * DOUTC];
__device__ float g_J[NN * DOUTC];
__device__ float g_Wc[64 * 320];
__device__ int g_counts[NN];
__device__ int g_rowoff[NN + 1];
__device__ int g_cursor[NN];
__device__ int g_bsums[128];
__device__ unsigned g_sorted[EE];

// ---------------- small kernels ----------------

// pack edge_embed [5,64,64] -> Wc [64][320] with column index t*64+o
__global__ void pack_k(const float* __restrict__ ee, float* __restrict__ Wc) {
    int idx = blockIdx.x * blockDim.x + threadIdx.x;
    if (idx >= 5 * 64 * 64) return;
    int t = idx >> 12;          // /4096
    int r = (idx >> 6) & 63;    // hin
    int o = idx & 63;           // hout
    Wc[r * 320 + t * 64 + o] = ee[idx];
}

// out0 = h = relu(x @ lin0_w + lin0_b), K=15
__global__ void lin0_k(const float* __restrict__ x, const float* __restrict__ w,
                       const float* __restrict__ b, float* __restrict__ h,
                       float* __restrict__ out0) {
    __shared__ float ws[15 * 64];
    __shared__ float bs[64];
    for (int i = threadIdx.x; i < 15 * 64; i += blockDim.x) ws[i] = w[i];
    if (threadIdx.x < 64) bs[threadIdx.x] = b[threadIdx.x];
    __syncthreads();
    int idx = blockIdx.x * blockDim.x + threadIdx.x;
    if (idx >= NN * 64) return;
    int n = idx >> 6, j = idx & 63;
    float s = bs[j];
    const float* xr = x + n * 15;
#pragma unroll
    for (int k = 0; k < 15; k++) s += xr[k] * ws[k * 64 + j];
    s = fmaxf(s, 0.f);
    h[idx] = s;
    out0[idx] = s;
}

__global__ void hist_k(const int* __restrict__ dst, int* __restrict__ counts) {
    int e = blockIdx.x * blockDim.x + threadIdx.x;
    if (e < EE) atomicAdd(&counts[dst[e]], 1);
}

__global__ void scan1(const int* __restrict__ counts, int* __restrict__ rowoff,
                      int* __restrict__ bsums) {
    __shared__ int sm[1024];
    int b = blockIdx.x, t = threadIdx.x;
    int i = b * 1024 + t;
    int v = (i < NN) ? counts[i] : 0;
    sm[t] = v;
    __syncthreads();
    for (int off = 1; off < 1024; off <<= 1) {
        int xv = (t >= off) ? sm[t - off] : 0;
        __syncthreads();
        sm[t] += xv;
        __syncthreads();
    }
    if (i < NN) rowoff[i] = sm[t] - v;  // exclusive
    if (t == 1023) bsums[b] = sm[t];
}

__global__ void scan2(int* __restrict__ bsums, int* __restrict__ rowoff, int nb) {
    if (threadIdx.x == 0 && blockIdx.x == 0) {
        int run = 0;
        for (int b = 0; b < nb; b++) { int tv = bsums[b]; bsums[b] = run; run += tv; }
        rowoff[NN] = run;  // == EE
    }
}

__global__ void scan3(int* __restrict__ rowoff, const int* __restrict__ bsums) {
    int i = blockIdx.x * blockDim.x + threadIdx.x;
    if (i < NN) rowoff[i] += bsums[i >> 10];
}

__global__ void fill_k(const int* __restrict__ src, const int* __restrict__ dst,
                       const int* __restrict__ typ, int* __restrict__ cursor,
                       unsigned* __restrict__ sorted) {
    int e = blockIdx.x * blockDim.x + threadIdx.x;
    if (e < EE) {
        int p = atomicAdd(&cursor[dst[e]], 1);
        sorted[p] = (unsigned)src[e] | ((unsigned)typ[e] << 17);
    }
}

// one warp per dst node: m[n] = relu( (sum_e T[src_e, type_e]) / deg + conv_bias )
__global__ void agg_k(const unsigned* __restrict__ sorted, const int* __restrict__ rowoff,
                      const int* __restrict__ counts, const float* __restrict__ T,
                      const float* __restrict__ cbias, float* __restrict__ m) {
    int w = (int)((blockIdx.x * blockDim.x + threadIdx.x) >> 5);
    int lane = threadIdx.x & 31;
    if (w >= NN) return;
    int s = rowoff[w], e = rowoff[w + 1];
    const float2* T2 = (const float2*)T;
    float ax = 0.f, ay = 0.f;
    int i = s;
    for (; i + 2 <= e; i += 2) {
        unsigned m0v = sorted[i], m1v = sorted[i + 1];
        float2 v0 = T2[(m0v & 0x1FFFFu) * 160u + (m0v >> 17) * 32u + lane];
        float2 v1 = T2[(m1v & 0x1FFFFu) * 160u + (m1v >> 17) * 32u + lane];
        ax += v0.x + v1.x;
        ay += v0.y + v1.y;
    }
    if (i < e) {
        unsigned mv = sorted[i];
        float2 v = T2[(mv & 0x1FFFFu) * 160u + (mv >> 17) * 32u + lane];
        ax += v.x; ay += v.y;
    }
    float inv = 1.f / fmaxf((float)counts[w], 1.f);
    float2 b = ((const float2*)cbias)[lane];
    float2 o;
    o.x = fmaxf(ax * inv + b.x, 0.f);
    o.y = fmaxf(ay * inv + b.y, 0.f);
    ((float2*)m)[w * 32 + lane] = o;
}

// GRU cell elementwise (torch gate order r,z,n); updates h in place
__global__ void gru_k(const float* __restrict__ gx, const float* __restrict__ gh,
                      float* __restrict__ h) {
    int idx = blockIdx.x * blockDim.x + threadIdx.x;
    if (idx >= NN * 64) return;
    int n = idx >> 6, j = idx & 63;
    const float* px = gx + n * 192;
    const float* ph = gh + n * 192;
    float r = 1.f / (1.f + __expf(-(px[j] + ph[j])));
    float z = 1.f / (1.f + __expf(-(px[64 + j] + ph[64 + j])));
    float t = tanhf(px[128 + j] + r * ph[128 + j]);
    float hv = h[idx];
    h[idx] = (1.f - z) * t + z * hv;
}

// gated = I*J, scatter-add by batch
__global__ void final_k(const float* __restrict__ I, const float* __restrict__ J,
                        const int* __restrict__ batch, float* __restrict__ out) {
    int idx = blockIdx.x * blockDim.x + threadIdx.x;
    if (idx >= NN * 12) return;
    int n = idx / 12;
    int j = idx - n * 12;
    atomicAdd(&out[batch[n] * 12 + j], I[idx] * J[idx]);
}

// ---------------- GEMM: C[M,Q] = act( A[M,64] @ B[64,Q] + bias (+ Cin) ) ----------------
// tile 128x64, 256 threads, 8x4 microtile, K fixed at 64.
// act: 0 none, 1 relu, 2 sigmoid.
__global__ void __launch_bounds__(256, 2)
gemm64(const float* __restrict__ A, const float* __restrict__ B,
       const float* __restrict__ bias, const float* __restrict__ Cin,
       float* __restrict__ C, int M, int Q, int act) {
    __shared__ float As[8][128];
    __shared__ float Bs[8][64];
    int tid = threadIdx.x;
    int tx = tid & 15, ty = tid >> 4;
    int m0 = blockIdx.y * 128, q0 = blockIdx.x * 64;

    float acc[8][4];
#pragma unroll
    for (int i = 0; i < 8; i++)
#pragma unroll
        for (int j = 0; j < 4; j++) acc[i][j] = 0.f;

    int arow = tid >> 1;
    int akoff = (tid & 1) * 4;

    for (int kc = 0; kc < 64; kc += 8) {
        float4 av = make_float4(0.f, 0.f, 0.f, 0.f);
        int gr = m0 + arow;
        if (gr < M) av = *(const float4*)(A + (size_t)gr * 64 + kc + akoff);
        As[akoff + 0][arow] = av.x;
        As[akoff + 1][arow] = av.y;
        As[akoff + 2][arow] = av.z;
        As[akoff + 3][arow] = av.w;
        if (tid < 128) {
            int k = tid >> 4;
            int qq = (tid & 15) * 4;
            float4 bv = make_float4(0.f, 0.f, 0.f, 0.f);
            if (q0 + qq < Q) bv = *(const float4*)(B + (size_t)(kc + k) * Q + q0 + qq);
            *(float4*)&Bs[k][qq] = bv;
        }
        __syncthreads();
#pragma unroll
        for (int k = 0; k < 8; k++) {
            float4 a0 = *(float4*)&As[k][ty * 8];
            float4 a1 = *(float4*)&As[k][ty * 8 + 4];
            float4 b = *(float4*)&Bs[k][tx * 4];
            float a[8] = {a0.x, a0.y, a0.z, a0.w, a1.x, a1.y, a1.z, a1.w};
#pragma unroll
            for (int i = 0; i < 8; i++) {
                acc[i][0] += a[i] * b.x;
                acc[i][1] += a[i] * b.y;
                acc[i][2] += a[i] * b.z;
                acc[i][3] += a[i] * b.w;
            }
        }
        __syncthreads();
    }

    int qc = q0 + tx * 4;
    if (qc >= Q) return;
    float4 bv = make_float4(0.f, 0.f, 0.f, 0.f);
    if (bias) bv = *(const float4*)(bias + qc);
#pragma unroll
    for (int i = 0; i < 8; i++) {
        int r = m0 + ty * 8 + i;
        if (r >= M) break;
        float4 v;
        v.x = acc[i][0] + bv.x;
        v.y = acc[i][1] + bv.y;
        v.z = acc[i][2] + bv.z;
        v.w = acc[i][3] + bv.w;
        if (Cin) {
            float4 c = *(const float4*)(Cin + (size_t)r * Q + qc);
            v.x += c.x; v.y += c.y; v.z += c.z; v.w += c.w;
        }
        if (act == 1) {
            v.x = fmaxf(v.x, 0.f); v.y = fmaxf(v.y, 0.f);
            v.z = fmaxf(v.z, 0.f); v.w = fmaxf(v.w, 0.f);
        } else if (act == 2) {
            v.x = 1.f / (1.f + __expf(-v.x));
            v.y = 1.f / (1.f + __expf(-v.y));
            v.z = 1.f / (1.f + __expf(-v.z));
            v.w = 1.f / (1.f + __expf(-v.w));
        }
        *(float4*)(C + (size_t)r * Q + qc) = v;
    }
}

// ---------------- launch ----------------
extern "C" void kernel_launch(void* const* d_in, const int* in_sizes, int n_in,
                              void* d_out, int out_size) {
    const float* x      = (const float*)d_in[0];
    const int*   ei     = (const int*)d_in[1];   // [2,E]: src then dst
    const int*   ea     = (const int*)d_in[2];
    const int*   batch  = (const int*)d_in[3];
    const float* lin0_w = (const float*)d_in[4];
    const float* lin0_b = (const float*)d_in[5];
    const float* ee     = (const float*)d_in[6];
    const float* cbias  = (const float*)d_in[7];
    const float* wih    = (const float*)d_in[8];
    const float* whh    = (const float*)d_in[9];
    const float* bih    = (const float*)d_in[10];
    const float* bhh    = (const float*)d_in[11];
    const float* iw1    = (const float*)d_in[12];
    const float* ib1    = (const float*)d_in[13];
    const float* iw2    = (const float*)d_in[14];
    const float* ib2    = (const float*)d_in[15];
    const float* jw1    = (const float*)d_in[16];
    const float* jb1    = (const float*)d_in[17];
    const float* jw2    = (const float*)d_in[18];
    const float* jb2    = (const float*)d_in[19];
    float* out = (float*)d_out;

    float *h, *out0, *T, *m, *gx, *gh, *A1, *I, *J, *Wc;
    int *counts, *rowoff, *cursor, *bsums;
    unsigned* sorted;
    cudaGetSymbolAddress((void**)&h, g_h);
    cudaGetSymbolAddress((void**)&out0, g_out0);
    cudaGetSymbolAddress((void**)&T, g_T);
    cudaGetSymbolAddress((void**)&m, g_m);
    cudaGetSymbolAddress((void**)&gx, g_gx);
    cudaGetSymbolAddress((void**)&gh, g_gh);
    cudaGetSymbolAddress((void**)&A1, g_A1);
    cudaGetSymbolAddress((void**)&I, g_I);
    cudaGetSymbolAddress((void**)&J, g_J);
    cudaGetSymbolAddress((void**)&Wc, g_Wc);
    cudaGetSymbolAddress((void**)&counts, g_counts);
    cudaGetSymbolAddress((void**)&rowoff, g_rowoff);
    cudaGetSymbolAddress((void**)&cursor, g_cursor);
    cudaGetSymbolAddress((void**)&bsums, g_bsums);
    cudaGetSymbolAddress((void**)&sorted, g_sorted);

    cudaStream_t s = 0;
    const int nb = (NN + 1023) / 1024;

    cudaMemsetAsync(counts, 0, NN * sizeof(int), s);
    pack_k<<<(5 * 64 * 64 + 255) / 256, 256, 0, s>>>(ee, Wc);
    lin0_k<<<(NN * 64 + 255) / 256, 256, 0, s>>>(x, lin0_w, lin0_b, h, out0);
    hist_k<<<(EE + 255) / 256, 256, 0, s>>>(ei + EE, counts);
    scan1<<<nb, 1024, 0, s>>>(counts, rowoff, bsums);
    scan2<<<1, 32, 0, s>>>(bsums, rowoff, nb);
    scan3<<<(NN + 255) / 256, 256, 0, s>>>(rowoff, bsums);
    cudaMemcpyAsync(cursor, rowoff, NN * sizeof(int), cudaMemcpyDeviceToDevice, s);
    fill_k<<<(EE + 255) / 256, 256, 0, s>>>(ei, ei + EE, ea, cursor, sorted);

    dim3 gT(5, (NN + 127) / 128);
    dim3 g3(3, (NN + 127) / 128);
    dim3 g1(1, (NN + 127) / 128);

    for (int step = 0; step < 6; step++) {
        gemm64<<<gT, 256, 0, s>>>(h, Wc, nullptr, nullptr, T, NN, 320, 0);
        agg_k<<<(NN * 32 + 255) / 256, 256, 0, s>>>(sorted, rowoff, counts, T, cbias, m);
        gemm64<<<g3, 256, 0, s>>>(m, wih, bih, nullptr, gx, NN, 192, 0);
        gemm64<<<g3, 256, 0, s>>>(h, whh, bhh, nullptr, gh, NN, 192, 0);
        gru_k<<<(NN * 64 + 255) / 256, 256, 0, s>>>(gx, gh, h);
    }

    // readout
    gemm64<<<g1, 256, 0, s>>>(h, iw1, ib1, nullptr, A1, NN, 64, 0);            // A1 = h@iw1[0:64] + b
    gemm64<<<g1, 256, 0, s>>>(out0, iw1 + 64 * 64, nullptr, A1, A1, NN, 64, 2); // A1 = sig(A1 + out0@iw1[64:128])
    gemm64<<<g1, 256, 0, s>>>(A1, iw2, ib2, nullptr, I, NN, 12, 2);            // I = sig(A1@iw2 + b)
    gemm64<<<g1, 256, 0, s>>>(h, jw1, jb1, nullptr, m, NN, 64, 2);             // B1 = sig(h@jw1 + b), reuse m
    gemm64<<<g1, 256, 0, s>>>(m, jw2, jb2, nullptr, J, NN, 12, 0);             // J = B1@jw2 + b

    cudaMemsetAsync(out, 0, GGB * DOUTC * sizeof(float), s);
    final_k<<<(NN * 12 + 255) / 256, 256, 0, s>>>(I, J, batch, out);
}